// round 2
// baseline (speedup 1.0000x reference)
#include <cuda_runtime.h>
#include <cuda_fp16.h>
#include <cstdint>

#define OUT_F 11008
#define IN_F  4096
#define M_ROWS 8192

// ---------------------------------------------------------------------------
// Scratch (device globals: allocation-free rule)
// ---------------------------------------------------------------------------
__device__ __half g_Wh[(size_t)OUT_F * IN_F];   // dequantized W, fp16, [O, I] K-major
__device__ __half g_Xh[(size_t)M_ROWS * IN_F];  // x in fp16, [M, K] K-major

__constant__ float c_code[16] = {
    -1.0f, -0.6961928009986877f, -0.5250730514526367f, -0.39491748809814453f,
    -0.28444138169288635f, -0.18477343022823334f, -0.09105003625154495f, 0.0f,
    0.07958029955625534f, 0.16093020141124725f, 0.24611230194568634f,
    0.33791524171829224f, 0.44070982933044434f, 0.5626170039176941f,
    0.7229568362236023f, 1.0f };

// ---------------------------------------------------------------------------
// Prep kernels
// ---------------------------------------------------------------------------
__global__ void dequant_w_kernel(const int* __restrict__ idx, const float* __restrict__ absmax) {
    size_t t = (size_t)blockIdx.x * blockDim.x + threadIdx.x;   // 8 weights / thread
    size_t base = t * 8;
    float am = __ldg(&absmax[base >> 6]);
    int4 a = reinterpret_cast<const int4*>(idx)[t * 2 + 0];
    int4 b = reinterpret_cast<const int4*>(idx)[t * 2 + 1];
    __half2 h[4];
    h[0] = __floats2half2_rn(c_code[a.x] * am, c_code[a.y] * am);
    h[1] = __floats2half2_rn(c_code[a.z] * am, c_code[a.w] * am);
    h[2] = __floats2half2_rn(c_code[b.x] * am, c_code[b.y] * am);
    h[3] = __floats2half2_rn(c_code[b.z] * am, c_code[b.w] * am);
    *reinterpret_cast<uint4*>(&g_Wh[base]) = *reinterpret_cast<uint4*>(h);
}

__global__ void cvt_x_kernel(const float* __restrict__ x) {
    size_t t = (size_t)blockIdx.x * blockDim.x + threadIdx.x;   // 4 floats / thread
    float4 v = reinterpret_cast<const float4*>(x)[t];
    __half2 h[2];
    h[0] = __floats2half2_rn(v.x, v.y);
    h[1] = __floats2half2_rn(v.z, v.w);
    *reinterpret_cast<uint2*>(&g_Xh[t * 4]) = *reinterpret_cast<uint2*>(h);
}

// ---------------------------------------------------------------------------
// GEMM: sm_80-style multistage mma.sync pipeline (baseline PTX — no tcgen05)
//   C[M,N] = A[M,K] * B[N,K]^T   (both K-major -> mma .row.col)
//   CTA tile 128x256x64, 8 warps (2 M x 4 N), warp tile 64x64, 4-stage cp.async
// ---------------------------------------------------------------------------
static constexpr int BM = 128, BN = 256, BK = 64, STAGES = 4;
static constexpr int A_BYTES = BM * BK * 2;                 // 16384
static constexpr int B_BYTES = BN * BK * 2;                 // 32768
static constexpr int STAGE_BYTES = A_BYTES + B_BYTES;       // 49152
static constexpr int SMEM_DYN = STAGES * STAGE_BYTES;       // 196608 (192 KB)
static constexpr int K_ITERS = IN_F / BK;                   // 64

__device__ __forceinline__ uint32_t smem_u32(const void* p) {
    uint32_t a;
    asm("{ .reg .u64 t; cvta.to.shared.u64 t, %1; cvt.u32.u64 %0, t; }" : "=r"(a) : "l"(p));
    return a;
}
__device__ __forceinline__ void cp16(uint32_t s, const void* g) {
    asm volatile("cp.async.cg.shared.global [%0], [%1], 16;" :: "r"(s), "l"(g) : "memory");
}
__device__ __forceinline__ void cp_commit() {
    asm volatile("cp.async.commit_group;" ::: "memory");
}
template <int N>
__device__ __forceinline__ void cp_wait() {
    asm volatile("cp.async.wait_group %0;" :: "n"(N) : "memory");
}
__device__ __forceinline__ void ldsm4(uint32_t* r, uint32_t a) {
    asm volatile("ldmatrix.sync.aligned.m8n8.x4.shared.b16 {%0,%1,%2,%3}, [%4];"
        : "=r"(r[0]), "=r"(r[1]), "=r"(r[2]), "=r"(r[3]) : "r"(a));
}
__device__ __forceinline__ void mma16816(float* c, const uint32_t* a, uint32_t b0, uint32_t b1) {
    asm volatile(
        "mma.sync.aligned.m16n8k16.row.col.f32.f16.f16.f32 "
        "{%0,%1,%2,%3}, {%4,%5,%6,%7}, {%8,%9}, {%0,%1,%2,%3};"
        : "+f"(c[0]), "+f"(c[1]), "+f"(c[2]), "+f"(c[3])
        : "r"(a[0]), "r"(a[1]), "r"(a[2]), "r"(a[3]), "r"(b0), "r"(b1));
}

__global__ void __launch_bounds__(256, 1)
gemm_kernel(const float* __restrict__ bias, float* __restrict__ out)
{
    extern __shared__ char smem_raw[];
    const uint32_t smem = smem_u32(smem_raw);
    const int tid = threadIdx.x, wid = tid >> 5, lane = tid & 31;
    const int m0 = blockIdx.y * BM, n0 = blockIdx.x * BN;

    // ---- loader mapping: thread t -> row t/8 (+32 per pass), 16B chunk t%8 ----
    const int lrow = tid >> 3;                               // 0..31
    const int lchk = tid & 7;                                // 0..7
    const uint32_t ld_soff = (uint32_t)lrow * 128 + (uint32_t)((lchk ^ (lrow & 7)) << 4);
    const __half* gA0 = &g_Xh[(size_t)(m0 + lrow) * IN_F + lchk * 8];
    const __half* gB0 = &g_Wh[(size_t)(n0 + lrow) * IN_F + lchk * 8];

    // ---- compute mapping: warp (wid&1) x (wid>>2? no: wid/2) -> 64x64 tile ----
    const int wm = (wid & 1) * 64;
    const int wn = (wid >> 1) * 64;
    const int lr = lane & 15, hi = lane >> 4, lo = lane & 7;

    uint32_t a_base[4], b_base[4];
    #pragma unroll
    for (int mi = 0; mi < 4; mi++) a_base[mi] = (uint32_t)(wm + mi * 16 + lr) * 128;
    #pragma unroll
    for (int ni = 0; ni < 4; ni++) b_base[ni] = (uint32_t)A_BYTES + (uint32_t)(wn + ni * 16 + lr) * 128;

    float acc[4][8][4];
    #pragma unroll
    for (int mi = 0; mi < 4; mi++)
        #pragma unroll
        for (int nj = 0; nj < 8; nj++)
            #pragma unroll
            for (int r = 0; r < 4; r++) acc[mi][nj][r] = 0.0f;

    // ---- prologue: fill STAGES-1 stages ----
    #pragma unroll
    for (int s = 0; s < STAGES - 1; s++) {
        uint32_t base = smem + s * STAGE_BYTES;
        #pragma unroll
        for (int p = 0; p < 4; p++)
            cp16(base + ld_soff + p * 32 * 128, gA0 + (size_t)s * BK + (size_t)p * 32 * IN_F);
        #pragma unroll
        for (int p = 0; p < 8; p++)
            cp16(base + A_BYTES + ld_soff + p * 32 * 128, gB0 + (size_t)s * BK + (size_t)p * 32 * IN_F);
        cp_commit();
    }

    // ---- mainloop ----
    for (int kt = 0; kt < K_ITERS; kt++) {
        cp_wait<STAGES - 2>();
        __syncthreads();

        // issue next stage load (overwrites slot consumed at iter kt-1)
        int nxt = kt + STAGES - 1;
        if (nxt < K_ITERS) {
            uint32_t base = smem + (nxt & (STAGES - 1)) * STAGE_BYTES;
            #pragma unroll
            for (int p = 0; p < 4; p++)
                cp16(base + ld_soff + p * 32 * 128, gA0 + (size_t)nxt * BK + (size_t)p * 32 * IN_F);
            #pragma unroll
            for (int p = 0; p < 8; p++)
                cp16(base + A_BYTES + ld_soff + p * 32 * 128, gB0 + (size_t)nxt * BK + (size_t)p * 32 * IN_F);
        }
        cp_commit();

        // compute on stage kt
        const uint32_t sbase = smem + (kt & (STAGES - 1)) * STAGE_BYTES;
        #pragma unroll
        for (int ks = 0; ks < BK / 16; ks++) {
            const uint32_t swz = (uint32_t)(((ks * 2 + hi) ^ lo) << 4);
            uint32_t a[4][4], b[4][4];
            #pragma unroll
            for (int mi = 0; mi < 4; mi++) ldsm4(a[mi], sbase + a_base[mi] + swz);
            #pragma unroll
            for (int ni = 0; ni < 4; ni++) ldsm4(b[ni], sbase + b_base[ni] + swz);
            #pragma unroll
            for (int mi = 0; mi < 4; mi++) {
                #pragma unroll
                for (int ni = 0; ni < 4; ni++) {
                    // ldsm4 on a 16x16 B tile: {r0,r1,r2,r3} = {b0(n lo8), b0(n hi8), b1(n lo8), b1(n hi8)}
                    mma16816(acc[mi][2 * ni + 0], a[mi], b[ni][0], b[ni][2]);
                    mma16816(acc[mi][2 * ni + 1], a[mi], b[ni][1], b[ni][3]);
                }
            }
        }
    }

    // ---- epilogue: C layout m16n8 -> lane row = l/4 (+8), cols 2*(l%4)+{0,1} ----
    const int er = m0 + wm + (lane >> 2);
    const int ec = n0 + wn + ((lane & 3) << 1);
    #pragma unroll
    for (int mi = 0; mi < 4; mi++) {
        #pragma unroll
        for (int nj = 0; nj < 8; nj++) {
            const int row = er + mi * 16;
            const int col = ec + nj * 8;
            float2 bv = *reinterpret_cast<const float2*>(&bias[col]);
            float2 v0 = { acc[mi][nj][0] + bv.x, acc[mi][nj][1] + bv.y };
            float2 v1 = { acc[mi][nj][2] + bv.x, acc[mi][nj][3] + bv.y };
            *reinterpret_cast<float2*>(&out[(size_t)row * OUT_F + col]) = v0;
            *reinterpret_cast<float2*>(&out[(size_t)(row + 8) * OUT_F + col]) = v1;
        }
    }
}

// ---------------------------------------------------------------------------
// Host
// ---------------------------------------------------------------------------
extern "C" void kernel_launch(void* const* d_in, const int* in_sizes, int n_in,
                              void* d_out, int out_size)
{
    const float* x      = (const float*)d_in[0];
    const int*   w_idx  = (const int*)d_in[1];
    const float* absmax = (const float*)d_in[2];
    const float* bias   = (const float*)d_in[3];
    float*       out    = (float*)d_out;

    // prep: dequant W (8 weights/thread), convert x (4 floats/thread)
    dequant_w_kernel<<<(OUT_F * (size_t)IN_F) / 8 / 256, 256>>>(w_idx, absmax);
    cvt_x_kernel<<<(M_ROWS * (size_t)IN_F) / 4 / 256, 256>>>(x);

    static bool attr_set = false;  // host-side attribute set is idempotent & capture-safe
    cudaFuncSetAttribute(gemm_kernel, cudaFuncAttributeMaxDynamicSharedMemorySize, SMEM_DYN);

    dim3 grid(OUT_F / BN, M_ROWS / BM);   // 43 x 64
    gemm_kernel<<<grid, 256, SMEM_DYN>>>(bias, out);
    (void)attr_set; (void)in_sizes; (void)n_in; (void)out_size;
}

// round 3
// speedup vs baseline: 1.0018x; 1.0018x over previous
#include <cuda_runtime.h>
#include <cuda_fp16.h>
#include <cstdint>

#define OUT_F 11008
#define IN_F  4096
#define M_ROWS 8192

// ---------------------------------------------------------------------------
// Scratch (device globals: allocation-free rule)
// ---------------------------------------------------------------------------
__device__ __half g_Wh[(size_t)OUT_F * IN_F];   // dequantized W, fp16, [O, I] K-major
__device__ __half g_Xh[(size_t)M_ROWS * IN_F];  // x in fp16, [M, K] K-major

__constant__ float c_code[16] = {
    -1.0f, -0.6961928009986877f, -0.5250730514526367f, -0.39491748809814453f,
    -0.28444138169288635f, -0.18477343022823334f, -0.09105003625154495f, 0.0f,
    0.07958029955625534f, 0.16093020141124725f, 0.24611230194568634f,
    0.33791524171829224f, 0.44070982933044434f, 0.5626170039176941f,
    0.7229568362236023f, 1.0f };

// ---------------------------------------------------------------------------
// Prep kernels — MLP-4 variants (B300: MLP>=4 fully overlaps latency)
// ---------------------------------------------------------------------------
__global__ void dequant_w_kernel(const int* __restrict__ idx, const float* __restrict__ absmax) {
    size_t t = (size_t)blockIdx.x * blockDim.x + threadIdx.x;   // 16 weights / thread
    size_t base = t * 16;
    float am = __ldg(&absmax[t >> 2]);                          // 16 weights within one 64-block
    int4 q0 = __ldcs(&reinterpret_cast<const int4*>(idx)[t * 4 + 0]);
    int4 q1 = __ldcs(&reinterpret_cast<const int4*>(idx)[t * 4 + 1]);
    int4 q2 = __ldcs(&reinterpret_cast<const int4*>(idx)[t * 4 + 2]);
    int4 q3 = __ldcs(&reinterpret_cast<const int4*>(idx)[t * 4 + 3]);
    __half2 h[8];
    h[0] = __floats2half2_rn(c_code[q0.x] * am, c_code[q0.y] * am);
    h[1] = __floats2half2_rn(c_code[q0.z] * am, c_code[q0.w] * am);
    h[2] = __floats2half2_rn(c_code[q1.x] * am, c_code[q1.y] * am);
    h[3] = __floats2half2_rn(c_code[q1.z] * am, c_code[q1.w] * am);
    h[4] = __floats2half2_rn(c_code[q2.x] * am, c_code[q2.y] * am);
    h[5] = __floats2half2_rn(c_code[q2.z] * am, c_code[q2.w] * am);
    h[6] = __floats2half2_rn(c_code[q3.x] * am, c_code[q3.y] * am);
    h[7] = __floats2half2_rn(c_code[q3.z] * am, c_code[q3.w] * am);
    uint4* dst = reinterpret_cast<uint4*>(&g_Wh[base]);
    __stcs(dst + 0, reinterpret_cast<uint4*>(h)[0]);
    __stcs(dst + 1, reinterpret_cast<uint4*>(h)[1]);
}

__global__ void cvt_x_kernel(const float* __restrict__ x) {
    size_t t = (size_t)blockIdx.x * blockDim.x + threadIdx.x;   // 8 floats / thread
    float4 v0 = __ldcs(&reinterpret_cast<const float4*>(x)[t * 2 + 0]);
    float4 v1 = __ldcs(&reinterpret_cast<const float4*>(x)[t * 2 + 1]);
    __half2 h[4];
    h[0] = __floats2half2_rn(v0.x, v0.y);
    h[1] = __floats2half2_rn(v0.z, v0.w);
    h[2] = __floats2half2_rn(v1.x, v1.y);
    h[3] = __floats2half2_rn(v1.z, v1.w);
    __stcs(reinterpret_cast<uint4*>(&g_Xh[t * 8]), *reinterpret_cast<uint4*>(h));
}

// ---------------------------------------------------------------------------
// GEMM: sm_80-style multistage mma.sync pipeline (baseline PTX — no tcgen05)
//   C[M,N] = A[M,K] * B[N,K]^T   (both K-major -> mma .row.col)
//   CTA tile 128x256x64, 8 warps (2 M x 4 N), warp tile 64x64, 4-stage cp.async
//   + fragment double-buffering, + GROUP_M rasterization
// ---------------------------------------------------------------------------
static constexpr int BM = 128, BN = 256, BK = 64, STAGES = 4;
static constexpr int A_BYTES = BM * BK * 2;                 // 16384
static constexpr int B_BYTES = BN * BK * 2;                 // 32768
static constexpr int STAGE_BYTES = A_BYTES + B_BYTES;       // 49152
static constexpr int SMEM_DYN = STAGES * STAGE_BYTES;       // 196608 (192 KB)
static constexpr int K_ITERS = IN_F / BK;                   // 64
static constexpr int TILES_M = M_ROWS / BM;                 // 64
static constexpr int TILES_N = OUT_F / BN;                  // 43
static constexpr int GROUP_M = 8;

__device__ __forceinline__ uint32_t smem_u32(const void* p) {
    uint32_t a;
    asm("{ .reg .u64 t; cvta.to.shared.u64 t, %1; cvt.u32.u64 %0, t; }" : "=r"(a) : "l"(p));
    return a;
}
__device__ __forceinline__ void cp16(uint32_t s, const void* g) {
    asm volatile("cp.async.cg.shared.global [%0], [%1], 16;" :: "r"(s), "l"(g) : "memory");
}
__device__ __forceinline__ void cp_commit() {
    asm volatile("cp.async.commit_group;" ::: "memory");
}
template <int N>
__device__ __forceinline__ void cp_wait() {
    asm volatile("cp.async.wait_group %0;" :: "n"(N) : "memory");
}
__device__ __forceinline__ void ldsm4(uint32_t* r, uint32_t a) {
    asm volatile("ldmatrix.sync.aligned.m8n8.x4.shared.b16 {%0,%1,%2,%3}, [%4];"
        : "=r"(r[0]), "=r"(r[1]), "=r"(r[2]), "=r"(r[3]) : "r"(a));
}
__device__ __forceinline__ void mma16816(float* c, const uint32_t* a, uint32_t b0, uint32_t b1) {
    asm volatile(
        "mma.sync.aligned.m16n8k16.row.col.f32.f16.f16.f32 "
        "{%0,%1,%2,%3}, {%4,%5,%6,%7}, {%8,%9}, {%0,%1,%2,%3};"
        : "+f"(c[0]), "+f"(c[1]), "+f"(c[2]), "+f"(c[3])
        : "r"(a[0]), "r"(a[1]), "r"(a[2]), "r"(a[3]), "r"(b0), "r"(b1));
}

__global__ void __launch_bounds__(256, 1)
gemm_kernel(const float* __restrict__ bias, float* __restrict__ out)
{
    extern __shared__ char smem_raw[];
    const uint32_t smem = smem_u32(smem_raw);
    const int tid = threadIdx.x, wid = tid >> 5, lane = tid & 31;

    // ---- GROUP_M rasterization: each wave covers ~8 M-tiles x ~18 N-tiles ----
    const int bid = blockIdx.x;
    const int per_group = GROUP_M * TILES_N;                 // 344
    const int grp = bid / per_group;
    const int rem = bid - grp * per_group;
    const int m0 = (grp * GROUP_M + (rem % GROUP_M)) * BM;
    const int n0 = (rem / GROUP_M) * BN;

    // ---- loader mapping: thread t -> row t/8 (+32 per pass), 16B chunk t%8 ----
    const int lrow = tid >> 3;                               // 0..31
    const int lchk = tid & 7;                                // 0..7
    const uint32_t ld_soff = (uint32_t)lrow * 128 + (uint32_t)((lchk ^ (lrow & 7)) << 4);
    const __half* gA0 = &g_Xh[(size_t)(m0 + lrow) * IN_F + lchk * 8];
    const __half* gB0 = &g_Wh[(size_t)(n0 + lrow) * IN_F + lchk * 8];

    // ---- compute mapping: 2 M-warps x 4 N-warps, warp tile 64x64 ----
    const int wm = (wid & 1) * 64;
    const int wn = (wid >> 1) * 64;
    const int lr = lane & 15, hi = lane >> 4, lo = lane & 7;

    uint32_t a_base[4], b_base[4];
    #pragma unroll
    for (int mi = 0; mi < 4; mi++) a_base[mi] = (uint32_t)(wm + mi * 16 + lr) * 128;
    #pragma unroll
    for (int ni = 0; ni < 4; ni++) b_base[ni] = (uint32_t)A_BYTES + (uint32_t)(wn + ni * 16 + lr) * 128;

    float acc[4][8][4];
    #pragma unroll
    for (int mi = 0; mi < 4; mi++)
        #pragma unroll
        for (int nj = 0; nj < 8; nj++)
            #pragma unroll
            for (int r = 0; r < 4; r++) acc[mi][nj][r] = 0.0f;

    // ---- prologue: fill STAGES-1 stages ----
    #pragma unroll
    for (int s = 0; s < STAGES - 1; s++) {
        uint32_t base = smem + s * STAGE_BYTES;
        #pragma unroll
        for (int p = 0; p < 4; p++)
            cp16(base + ld_soff + p * 32 * 128, gA0 + (size_t)s * BK + (size_t)p * 32 * IN_F);
        #pragma unroll
        for (int p = 0; p < 8; p++)
            cp16(base + A_BYTES + ld_soff + p * 32 * 128, gB0 + (size_t)s * BK + (size_t)p * 32 * IN_F);
        cp_commit();
    }

    uint32_t af[2][4][4], bf[2][4][4];   // double-buffered fragments

    // ---- mainloop ----
    for (int kt = 0; kt < K_ITERS; kt++) {
        cp_wait<STAGES - 2>();
        __syncthreads();

        // issue next stage load (overwrites slot consumed at iter kt-1)
        int nxt = kt + STAGES - 1;
        if (nxt < K_ITERS) {
            uint32_t base = smem + (nxt & (STAGES - 1)) * STAGE_BYTES;
            #pragma unroll
            for (int p = 0; p < 4; p++)
                cp16(base + ld_soff + p * 32 * 128, gA0 + (size_t)nxt * BK + (size_t)p * 32 * IN_F);
            #pragma unroll
            for (int p = 0; p < 8; p++)
                cp16(base + A_BYTES + ld_soff + p * 32 * 128, gB0 + (size_t)nxt * BK + (size_t)p * 32 * IN_F);
        }
        cp_commit();

        // compute on stage kt with fragment double-buffering
        const uint32_t sbase = smem + (kt & (STAGES - 1)) * STAGE_BYTES;
        {
            const uint32_t swz0 = (uint32_t)((hi ^ lo) << 4);   // ks=0
            #pragma unroll
            for (int mi = 0; mi < 4; mi++) ldsm4(af[0][mi], sbase + a_base[mi] + swz0);
            #pragma unroll
            for (int ni = 0; ni < 4; ni++) ldsm4(bf[0][ni], sbase + b_base[ni] + swz0);
        }
        #pragma unroll
        for (int ks = 0; ks < BK / 16; ks++) {
            const int cur = ks & 1, nx = cur ^ 1;
            if (ks < BK / 16 - 1) {
                const uint32_t swz = (uint32_t)((((ks + 1) * 2 + hi) ^ lo) << 4);
                #pragma unroll
                for (int mi = 0; mi < 4; mi++) ldsm4(af[nx][mi], sbase + a_base[mi] + swz);
                #pragma unroll
                for (int ni = 0; ni < 4; ni++) ldsm4(bf[nx][ni], sbase + b_base[ni] + swz);
            }
            #pragma unroll
            for (int mi = 0; mi < 4; mi++) {
                #pragma unroll
                for (int ni = 0; ni < 4; ni++) {
                    mma16816(acc[mi][2 * ni + 0], af[cur][mi], bf[cur][ni][0], bf[cur][ni][2]);
                    mma16816(acc[mi][2 * ni + 1], af[cur][mi], bf[cur][ni][1], bf[cur][ni][3]);
                }
            }
        }
    }

    // ---- epilogue: C layout m16n8 -> lane row = l/4 (+8), cols 2*(l%4)+{0,1} ----
    const int er = m0 + wm + (lane >> 2);
    const int ec = n0 + wn + ((lane & 3) << 1);
    #pragma unroll
    for (int mi = 0; mi < 4; mi++) {
        #pragma unroll
        for (int nj = 0; nj < 8; nj++) {
            const int row = er + mi * 16;
            const int col = ec + nj * 8;
            float2 bv = *reinterpret_cast<const float2*>(&bias[col]);
            float2 v0 = { acc[mi][nj][0] + bv.x, acc[mi][nj][1] + bv.y };
            float2 v1 = { acc[mi][nj][2] + bv.x, acc[mi][nj][3] + bv.y };
            *reinterpret_cast<float2*>(&out[(size_t)row * OUT_F + col]) = v0;
            *reinterpret_cast<float2*>(&out[(size_t)(row + 8) * OUT_F + col]) = v1;
        }
    }
}

// ---------------------------------------------------------------------------
// Host
// ---------------------------------------------------------------------------
extern "C" void kernel_launch(void* const* d_in, const int* in_sizes, int n_in,
                              void* d_out, int out_size)
{
    const float* x      = (const float*)d_in[0];
    const int*   w_idx  = (const int*)d_in[1];
    const float* absmax = (const float*)d_in[2];
    const float* bias   = (const float*)d_in[3];
    float*       out    = (float*)d_out;

    // prep: dequant W (16 weights/thread), convert x (8 floats/thread)
    dequant_w_kernel<<<(OUT_F * (size_t)IN_F) / 16 / 256, 256>>>(w_idx, absmax);
    cvt_x_kernel<<<(M_ROWS * (size_t)IN_F) / 8 / 256, 256>>>(x);

    cudaFuncSetAttribute(gemm_kernel, cudaFuncAttributeMaxDynamicSharedMemorySize, SMEM_DYN);

    gemm_kernel<<<TILES_M * TILES_N, 256, SMEM_DYN>>>(bias, out);
    (void)in_sizes; (void)n_in; (void)out_size;
}

// round 5
// speedup vs baseline: 1.0906x; 1.0886x over previous
#include <cuda_runtime.h>
#include <cuda_fp16.h>
#include <cstdint>

#define OUT_F 11008
#define IN_F  4096
#define M_ROWS 8192

// ---------------------------------------------------------------------------
// Scratch (device globals: allocation-free rule)
// ---------------------------------------------------------------------------
__device__ __half g_Wh[(size_t)OUT_F * IN_F];   // dequantized W, fp16, [O, I] K-major
__device__ __half g_Xh[(size_t)M_ROWS * IN_F];  // x in fp16, [M, K] K-major

__constant__ float c_code[16] = {
    -1.0f, -0.6961928009986877f, -0.5250730514526367f, -0.39491748809814453f,
    -0.28444138169288635f, -0.18477343022823334f, -0.09105003625154495f, 0.0f,
    0.07958029955625534f, 0.16093020141124725f, 0.24611230194568634f,
    0.33791524171829224f, 0.44070982933044434f, 0.5626170039176941f,
    0.7229568362236023f, 1.0f };

// ---------------------------------------------------------------------------
// Fused prep: blocks [0, WB) dequant W (16 w/thread, smem table — no LDC
// serialization), blocks [WB, WB+XB) convert x (8 f/thread).
// ---------------------------------------------------------------------------
static constexpr int WB = (int)((size_t)OUT_F * IN_F / 16 / 256);   // 11008
static constexpr int XB = (int)((size_t)M_ROWS * IN_F / 8 / 256);   // 16384

__global__ void __launch_bounds__(256)
prep_kernel(const float* __restrict__ x, const int* __restrict__ idx,
            const float* __restrict__ absmax)
{
    __shared__ float s_code[16];
    if (threadIdx.x < 16) s_code[threadIdx.x] = c_code[threadIdx.x];
    __syncthreads();

    const int bid = blockIdx.x;
    if (bid < WB) {
        size_t t = (size_t)bid * 256 + threadIdx.x;   // 16 weights / thread
        float am = __ldg(&absmax[t >> 2]);
        int4 q0 = __ldcs(&reinterpret_cast<const int4*>(idx)[t * 4 + 0]);
        int4 q1 = __ldcs(&reinterpret_cast<const int4*>(idx)[t * 4 + 1]);
        int4 q2 = __ldcs(&reinterpret_cast<const int4*>(idx)[t * 4 + 2]);
        int4 q3 = __ldcs(&reinterpret_cast<const int4*>(idx)[t * 4 + 3]);
        __half2 h[8];
        h[0] = __floats2half2_rn(s_code[q0.x] * am, s_code[q0.y] * am);
        h[1] = __floats2half2_rn(s_code[q0.z] * am, s_code[q0.w] * am);
        h[2] = __floats2half2_rn(s_code[q1.x] * am, s_code[q1.y] * am);
        h[3] = __floats2half2_rn(s_code[q1.z] * am, s_code[q1.w] * am);
        h[4] = __floats2half2_rn(s_code[q2.x] * am, s_code[q2.y] * am);
        h[5] = __floats2half2_rn(s_code[q2.z] * am, s_code[q2.w] * am);
        h[6] = __floats2half2_rn(s_code[q3.x] * am, s_code[q3.y] * am);
        h[7] = __floats2half2_rn(s_code[q3.z] * am, s_code[q3.w] * am);
        uint4* dst = reinterpret_cast<uint4*>(&g_Wh[t * 16]);
        __stcs(dst + 0, reinterpret_cast<uint4*>(h)[0]);
        __stcs(dst + 1, reinterpret_cast<uint4*>(h)[1]);
    } else {
        size_t t = (size_t)(bid - WB) * 256 + threadIdx.x;   // 8 floats / thread
        float4 v0 = __ldcs(&reinterpret_cast<const float4*>(x)[t * 2 + 0]);
        float4 v1 = __ldcs(&reinterpret_cast<const float4*>(x)[t * 2 + 1]);
        __half2 h[4];
        h[0] = __floats2half2_rn(v0.x, v0.y);
        h[1] = __floats2half2_rn(v0.z, v0.w);
        h[2] = __floats2half2_rn(v1.x, v1.y);
        h[3] = __floats2half2_rn(v1.z, v1.w);
        __stcs(reinterpret_cast<uint4*>(&g_Xh[t * 8]), *reinterpret_cast<uint4*>(h));
    }
}

// ---------------------------------------------------------------------------
// GEMM: mma.sync multistage pipeline, occupancy-2 variant.
//   C[M,N] = A[M,K] * B[N,K]^T  (both K-major -> mma .row.col)
//   CTA tile 128x128x64, 8 warps (2 M x 4 N), warp tile 64x32,
//   3-stage cp.async (96 KB/CTA), 2 CTAs/SM -> 4 warps/SMSP for latency hiding
// ---------------------------------------------------------------------------
static constexpr int BM = 128, BN = 128, BK = 64, STAGES = 3;
static constexpr int A_BYTES = BM * BK * 2;                 // 16384
static constexpr int B_BYTES = BN * BK * 2;                 // 16384
static constexpr int STAGE_BYTES = A_BYTES + B_BYTES;       // 32768
static constexpr int SMEM_DYN = STAGES * STAGE_BYTES;       // 98304 (96 KB)
static constexpr int K_ITERS = IN_F / BK;                   // 64
static constexpr int TILES_M = M_ROWS / BM;                 // 64
static constexpr int TILES_N = OUT_F / BN;                  // 86
static constexpr int GROUP_M = 8;

__device__ __forceinline__ uint32_t smem_u32(const void* p) {
    uint32_t a;
    asm("{ .reg .u64 t; cvta.to.shared.u64 t, %1; cvt.u32.u64 %0, t; }" : "=r"(a) : "l"(p));
    return a;
}
__device__ __forceinline__ void cp16(uint32_t s, const void* g) {
    asm volatile("cp.async.cg.shared.global [%0], [%1], 16;" :: "r"(s), "l"(g) : "memory");
}
__device__ __forceinline__ void cp_commit() {
    asm volatile("cp.async.commit_group;" ::: "memory");
}
template <int N>
__device__ __forceinline__ void cp_wait() {
    asm volatile("cp.async.wait_group %0;" :: "n"(N) : "memory");
}
__device__ __forceinline__ void ldsm4(uint32_t* r, uint32_t a) {
    asm volatile("ldmatrix.sync.aligned.m8n8.x4.shared.b16 {%0,%1,%2,%3}, [%4];"
        : "=r"(r[0]), "=r"(r[1]), "=r"(r[2]), "=r"(r[3]) : "r"(a));
}
__device__ __forceinline__ void mma16816(float* c, const uint32_t* a, uint32_t b0, uint32_t b1) {
    asm volatile(
        "mma.sync.aligned.m16n8k16.row.col.f32.f16.f16.f32 "
        "{%0,%1,%2,%3}, {%4,%5,%6,%7}, {%8,%9}, {%0,%1,%2,%3};"
        : "+f"(c[0]), "+f"(c[1]), "+f"(c[2]), "+f"(c[3])
        : "r"(a[0]), "r"(a[1]), "r"(a[2]), "r"(a[3]), "r"(b0), "r"(b1));
}

__global__ void __launch_bounds__(256, 2)
gemm_kernel(const float* __restrict__ bias, float* __restrict__ out)
{
    extern __shared__ char smem_raw[];
    const uint32_t smem = smem_u32(smem_raw);
    const int tid = threadIdx.x, wid = tid >> 5, lane = tid & 31;

    // ---- GROUP_M rasterization ----
    const int bid = blockIdx.x;
    const int per_group = GROUP_M * TILES_N;                 // 688
    const int grp = bid / per_group;
    const int rem = bid - grp * per_group;
    const int m0 = (grp * GROUP_M + (rem % GROUP_M)) * BM;
    const int n0 = (rem / GROUP_M) * BN;

    // ---- loader: thread t -> row t/8 (+32/pass), 16B chunk t%8; 4 passes A, 4 passes B ----
    const int lrow = tid >> 3;                               // 0..31
    const int lchk = tid & 7;                                // 0..7
    const uint32_t ld_soff = (uint32_t)lrow * 128 + (uint32_t)((lchk ^ (lrow & 7)) << 4);
    const __half* gA0 = &g_Xh[(size_t)(m0 + lrow) * IN_F + lchk * 8];
    const __half* gB0 = &g_Wh[(size_t)(n0 + lrow) * IN_F + lchk * 8];

    // ---- compute mapping: 2 M-warps x 4 N-warps, warp tile 64x32 ----
    const int wm = (wid & 1) * 64;
    const int wn = (wid >> 1) * 32;
    const int lr = lane & 15, hi = lane >> 4, lo = lane & 7;

    uint32_t a_base[4], b_base[2];
    #pragma unroll
    for (int mi = 0; mi < 4; mi++) a_base[mi] = (uint32_t)(wm + mi * 16 + lr) * 128;
    #pragma unroll
    for (int ni = 0; ni < 2; ni++) b_base[ni] = (uint32_t)A_BYTES + (uint32_t)(wn + ni * 16 + lr) * 128;

    float acc[4][4][4];
    #pragma unroll
    for (int mi = 0; mi < 4; mi++)
        #pragma unroll
        for (int nj = 0; nj < 4; nj++)
            #pragma unroll
            for (int r = 0; r < 4; r++) acc[mi][nj][r] = 0.0f;

    // ---- prologue: fill stages 0,1 ----
    #pragma unroll
    for (int s = 0; s < STAGES - 1; s++) {
        uint32_t base = smem + s * STAGE_BYTES;
        #pragma unroll
        for (int p = 0; p < 4; p++)
            cp16(base + ld_soff + p * 32 * 128, gA0 + (size_t)s * BK + (size_t)p * 32 * IN_F);
        #pragma unroll
        for (int p = 0; p < 4; p++)
            cp16(base + B_BYTES + ld_soff + p * 32 * 128, gB0 + (size_t)s * BK + (size_t)p * 32 * IN_F);
        cp_commit();
    }

    // ring pointers (avoid %3): sc = compute stage, sfill = fill stage
    uint32_t sc = smem;
    uint32_t sfill = smem + (STAGES - 1) * STAGE_BYTES;
    const uint32_t ring_end = smem + STAGES * STAGE_BYTES;

    // ---- mainloop ----
    for (int kt = 0; kt < K_ITERS; kt++) {
        cp_wait<STAGES - 2>();
        __syncthreads();

        int nxt = kt + STAGES - 1;
        if (nxt < K_ITERS) {
            #pragma unroll
            for (int p = 0; p < 4; p++)
                cp16(sfill + ld_soff + p * 32 * 128, gA0 + (size_t)nxt * BK + (size_t)p * 32 * IN_F);
            #pragma unroll
            for (int p = 0; p < 4; p++)
                cp16(sfill + B_BYTES + ld_soff + p * 32 * 128, gB0 + (size_t)nxt * BK + (size_t)p * 32 * IN_F);
        }
        cp_commit();
        sfill += STAGE_BYTES; if (sfill == ring_end) sfill = smem;

        #pragma unroll
        for (int ks = 0; ks < BK / 16; ks++) {
            const uint32_t swz = (uint32_t)(((ks * 2 + hi) ^ lo) << 4);
            uint32_t a[4][4], b[2][4];
            #pragma unroll
            for (int mi = 0; mi < 4; mi++) ldsm4(a[mi], sc + a_base[mi] + swz);
            #pragma unroll
            for (int ni = 0; ni < 2; ni++) ldsm4(b[ni], sc + b_base[ni] + swz);
            #pragma unroll
            for (int mi = 0; mi < 4; mi++) {
                #pragma unroll
                for (int ni = 0; ni < 2; ni++) {
                    mma16816(acc[mi][2 * ni + 0], a[mi], b[ni][0], b[ni][2]);
                    mma16816(acc[mi][2 * ni + 1], a[mi], b[ni][1], b[ni][3]);
                }
            }
        }
        sc += STAGE_BYTES; if (sc == ring_end) sc = smem;
    }

    // ---- epilogue ----
    const int er = m0 + wm + (lane >> 2);
    const int ec = n0 + wn + ((lane & 3) << 1);
    #pragma unroll
    for (int mi = 0; mi < 4; mi++) {
        #pragma unroll
        for (int nj = 0; nj < 4; nj++) {
            const int row = er + mi * 16;
            const int col = ec + nj * 8;
            float2 bv = *reinterpret_cast<const float2*>(&bias[col]);
            float2 v0 = { acc[mi][nj][0] + bv.x, acc[mi][nj][1] + bv.y };
            float2 v1 = { acc[mi][nj][2] + bv.x, acc[mi][nj][3] + bv.y };
            *reinterpret_cast<float2*>(&out[(size_t)row * OUT_F + col]) = v0;
            *reinterpret_cast<float2*>(&out[(size_t)(row + 8) * OUT_F + col]) = v1;
        }
    }
}

// ---------------------------------------------------------------------------
// Host
// ---------------------------------------------------------------------------
extern "C" void kernel_launch(void* const* d_in, const int* in_sizes, int n_in,
                              void* d_out, int out_size)
{
    const float* x      = (const float*)d_in[0];
    const int*   w_idx  = (const int*)d_in[1];
    const float* absmax = (const float*)d_in[2];
    const float* bias   = (const float*)d_in[3];
    float*       out    = (float*)d_out;

    prep_kernel<<<WB + XB, 256>>>(x, w_idx, absmax);

    cudaFuncSetAttribute(gemm_kernel, cudaFuncAttributeMaxDynamicSharedMemorySize, SMEM_DYN);
    gemm_kernel<<<TILES_M * TILES_N, 256, SMEM_DYN>>>(bias, out);
    (void)in_sizes; (void)n_in; (void)out_size;
}

// round 8
// speedup vs baseline: 1.1526x; 1.0569x over previous
#include <cuda_runtime.h>
#include <cuda_fp16.h>
#include <cstdint>

#define OUT_F 11008
#define IN_F  4096
#define M_ROWS 8192

static constexpr size_t W_ELEMS = (size_t)OUT_F * IN_F;
static constexpr size_t X_ELEMS = (size_t)M_ROWS * IN_F;

// Single merged scratch buffer: W fp16 at [0, W_ELEMS), X fp16 at [W_ELEMS, +X_ELEMS)
__device__ __half g_buf[W_ELEMS + X_ELEMS];

__constant__ float c_code[16] = {
    -1.0f, -0.6961928009986877f, -0.5250730514526367f, -0.39491748809814453f,
    -0.28444138169288635f, -0.18477343022823334f, -0.09105003625154495f, 0.0f,
    0.07958029955625534f, 0.16093020141124725f, 0.24611230194568634f,
    0.33791524171829224f, 0.44070982933044434f, 0.5626170039176941f,
    0.7229568362236023f, 1.0f };

// ---------------------------------------------------------------------------
// Fused prep: blocks [0, WB) dequant W (16 w/thread, smem NF4 table),
// blocks [WB, WB+XB) convert x (8 f/thread).
// ---------------------------------------------------------------------------
static constexpr int WB = (int)(W_ELEMS / 16 / 256);   // 11008
static constexpr int XB = (int)(X_ELEMS / 8 / 256);    // 16384

__global__ void __launch_bounds__(256)
prep_kernel(const float* __restrict__ x, const int* __restrict__ idx,
            const float* __restrict__ absmax)
{
    __shared__ float s_code[16];
    if (threadIdx.x < 16) s_code[threadIdx.x] = c_code[threadIdx.x];
    __syncthreads();

    const int bid = blockIdx.x;
    if (bid < WB) {
        size_t t = (size_t)bid * 256 + threadIdx.x;   // 16 weights / thread
        float am = __ldg(&absmax[t >> 2]);
        int4 q0 = __ldcs(&reinterpret_cast<const int4*>(idx)[t * 4 + 0]);
        int4 q1 = __ldcs(&reinterpret_cast<const int4*>(idx)[t * 4 + 1]);
        int4 q2 = __ldcs(&reinterpret_cast<const int4*>(idx)[t * 4 + 2]);
        int4 q3 = __ldcs(&reinterpret_cast<const int4*>(idx)[t * 4 + 3]);
        __half2 h[8];
        h[0] = __floats2half2_rn(s_code[q0.x] * am, s_code[q0.y] * am);
        h[1] = __floats2half2_rn(s_code[q0.z] * am, s_code[q0.w] * am);
        h[2] = __floats2half2_rn(s_code[q1.x] * am, s_code[q1.y] * am);
        h[3] = __floats2half2_rn(s_code[q1.z] * am, s_code[q1.w] * am);
        h[4] = __floats2half2_rn(s_code[q2.x] * am, s_code[q2.y] * am);
        h[5] = __floats2half2_rn(s_code[q2.z] * am, s_code[q2.w] * am);
        h[6] = __floats2half2_rn(s_code[q3.x] * am, s_code[q3.y] * am);
        h[7] = __floats2half2_rn(s_code[q3.z] * am, s_code[q3.w] * am);
        uint4* dst = reinterpret_cast<uint4*>(&g_buf[t * 16]);
        __stcs(dst + 0, reinterpret_cast<uint4*>(h)[0]);
        __stcs(dst + 1, reinterpret_cast<uint4*>(h)[1]);
    } else {
        size_t t = (size_t)(bid - WB) * 256 + threadIdx.x;   // 8 floats / thread
        float4 v0 = __ldcs(&reinterpret_cast<const float4*>(x)[t * 2 + 0]);
        float4 v1 = __ldcs(&reinterpret_cast<const float4*>(x)[t * 2 + 1]);
        __half2 h[4];
        h[0] = __floats2half2_rn(v0.x, v0.y);
        h[1] = __floats2half2_rn(v0.z, v0.w);
        h[2] = __floats2half2_rn(v1.x, v1.y);
        h[3] = __floats2half2_rn(v1.z, v1.w);
        __stcs(reinterpret_cast<uint4*>(&g_buf[W_ELEMS + t * 8]), *reinterpret_cast<uint4*>(h));
    }
}

// ---------------------------------------------------------------------------
// GEMM: mma.sync multistage, occ-2, fragment double-buffered, spread cp.async.
//   C[M,N] = A[M,K] * B[N,K]^T   CTA 128x128x64, 8 warps (2M x 4N), warp 64x32
// ---------------------------------------------------------------------------
static constexpr int BM = 128, BN = 128, BK = 64, STAGES = 3;
static constexpr int A_BYTES = BM * BK * 2;                 // 16384
static constexpr int STAGE_BYTES = 2 * A_BYTES;             // 32768
static constexpr int SMEM_DYN = STAGES * STAGE_BYTES;       // 98304
static constexpr int K_ITERS = IN_F / BK;                   // 64
static constexpr int TILES_M = M_ROWS / BM;                 // 64
static constexpr int TILES_N = OUT_F / BN;                  // 86
static constexpr int GROUP_M = 8;

__device__ __forceinline__ uint32_t smem_u32(const void* p) {
    uint32_t a;
    asm("{ .reg .u64 t; cvta.to.shared.u64 t, %1; cvt.u32.u64 %0, t; }" : "=r"(a) : "l"(p));
    return a;
}
__device__ __forceinline__ void cp16(uint32_t s, const void* g) {
    asm volatile("cp.async.cg.shared.global [%0], [%1], 16;" :: "r"(s), "l"(g) : "memory");
}
__device__ __forceinline__ void cp_commit() {
    asm volatile("cp.async.commit_group;" ::: "memory");
}
template <int N>
__device__ __forceinline__ void cp_wait() {
    asm volatile("cp.async.wait_group %0;" :: "n"(N) : "memory");
}
__device__ __forceinline__ void ldsm4(uint32_t* r, uint32_t a) {
    asm volatile("ldmatrix.sync.aligned.m8n8.x4.shared.b16 {%0,%1,%2,%3}, [%4];"
        : "=r"(r[0]), "=r"(r[1]), "=r"(r[2]), "=r"(r[3]) : "r"(a));
}
__device__ __forceinline__ void mma16816(float* c, const uint32_t* a, uint32_t b0, uint32_t b1) {
    asm volatile(
        "mma.sync.aligned.m16n8k16.row.col.f32.f16.f16.f32 "
        "{%0,%1,%2,%3}, {%4,%5,%6,%7}, {%8,%9}, {%0,%1,%2,%3};"
        : "+f"(c[0]), "+f"(c[1]), "+f"(c[2]), "+f"(c[3])
        : "r"(a[0]), "r"(a[1]), "r"(a[2]), "r"(a[3]), "r"(b0), "r"(b1));
}

__global__ void __launch_bounds__(256, 2)
gemm_kernel(const float* __restrict__ bias, float* __restrict__ out)
{
    extern __shared__ char smem_raw[];
    const uint32_t smem = smem_u32(smem_raw);
    const int tid = threadIdx.x, wid = tid >> 5, lane = tid & 31;

    // ---- GROUP_M rasterization ----
    const int bid = blockIdx.x;
    const int per_group = GROUP_M * TILES_N;
    const int grp = bid / per_group;
    const int rem = bid - grp * per_group;
    const int m0 = (grp * GROUP_M + (rem % GROUP_M)) * BM;
    const int n0 = (rem / GROUP_M) * BN;

    // ---- loader: thread t -> row t/8 (+32/pass), 16B chunk t%8 ----
    const int lrow = tid >> 3;
    const int lchk = tid & 7;
    const uint32_t ld_soff = (uint32_t)lrow * 128 + (uint32_t)((lchk ^ (lrow & 7)) << 4);
    // fill pointers (advance by BK per kt); B = W at offset 0, A = X at W_ELEMS
    const __half* gB = &g_buf[(size_t)(n0 + lrow) * IN_F + lchk * 8];
    const __half* gA = &g_buf[W_ELEMS + (size_t)(m0 + lrow) * IN_F + lchk * 8];

    // ---- compute mapping: 2 M-warps x 4 N-warps, warp tile 64x32 ----
    const int wm = (wid & 1) * 64;
    const int wn = (wid >> 1) * 32;
    const int lr = lane & 15, hi = lane >> 4, lo = lane & 7;

    uint32_t a_base[4], b_base[2];
    #pragma unroll
    for (int mi = 0; mi < 4; mi++) a_base[mi] = (uint32_t)(wm + mi * 16 + lr) * 128;
    #pragma unroll
    for (int ni = 0; ni < 2; ni++) b_base[ni] = (uint32_t)A_BYTES + (uint32_t)(wn + ni * 16 + lr) * 128;

    float acc[4][4][4];
    #pragma unroll
    for (int mi = 0; mi < 4; mi++)
        #pragma unroll
        for (int nj = 0; nj < 4; nj++)
            #pragma unroll
            for (int r = 0; r < 4; r++) acc[mi][nj][r] = 0.0f;

    // ---- prologue: fill stages 0,1 ----
    #pragma unroll
    for (int s = 0; s < STAGES - 1; s++) {
        uint32_t base = smem + s * STAGE_BYTES;
        #pragma unroll
        for (int p = 0; p < 4; p++) {
            cp16(base + ld_soff + p * 32 * 128,           gA + (size_t)s * BK + (size_t)p * 32 * IN_F);
            cp16(base + A_BYTES + ld_soff + p * 32 * 128, gB + (size_t)s * BK + (size_t)p * 32 * IN_F);
        }
        cp_commit();
    }
    gA += (STAGES - 1) * BK;      // now point at fill stage kt+2
    gB += (STAGES - 1) * BK;

    uint32_t sc = smem;
    uint32_t sfill = smem + (STAGES - 1) * STAGE_BYTES;
    const uint32_t ring_end = smem + STAGES * STAGE_BYTES;

    uint32_t af[2][4][4], bf[2][2][4];   // double-buffered fragments

    // ---- mainloop ----
    for (int kt = 0; kt < K_ITERS; kt++) {
        cp_wait<STAGES - 2>();
        __syncthreads();
        const bool fill = (kt + STAGES - 1 < K_ITERS);

        // frag prefetch for ks = 0
        {
            const uint32_t swz0 = (uint32_t)((hi ^ lo) << 4);
            #pragma unroll
            for (int mi = 0; mi < 4; mi++) ldsm4(af[0][mi], sc + a_base[mi] + swz0);
            #pragma unroll
            for (int ni = 0; ni < 2; ni++) ldsm4(bf[0][ni], sc + b_base[ni] + swz0);
        }

        #pragma unroll
        for (int ks = 0; ks < BK / 16; ks++) {
            const int cur = ks & 1, nx = cur ^ 1;
            if (ks < BK / 16 - 1) {
                const uint32_t swz = (uint32_t)((((ks + 1) * 2 + hi) ^ lo) << 4);
                #pragma unroll
                for (int mi = 0; mi < 4; mi++) ldsm4(af[nx][mi], sc + a_base[mi] + swz);
                #pragma unroll
                for (int ni = 0; ni < 2; ni++) ldsm4(bf[nx][ni], sc + b_base[ni] + swz);
            }
            // spread fill: 2 cp16 per ks step (A pass ks, B pass ks)
            if (fill) {
                cp16(sfill + ld_soff + ks * 32 * 128,           gA + (size_t)ks * 32 * IN_F);
                cp16(sfill + A_BYTES + ld_soff + ks * 32 * 128, gB + (size_t)ks * 32 * IN_F);
            }
            #pragma unroll
            for (int mi = 0; mi < 4; mi++) {
                #pragma unroll
                for (int ni = 0; ni < 2; ni++) {
                    mma16816(acc[mi][2 * ni + 0], af[cur][mi], bf[cur][ni][0], bf[cur][ni][2]);
                    mma16816(acc[mi][2 * ni + 1], af[cur][mi], bf[cur][ni][1], bf[cur][ni][3]);
                }
            }
        }
        cp_commit();
        sc += STAGE_BYTES;    if (sc == ring_end) sc = smem;
        sfill += STAGE_BYTES; if (sfill == ring_end) sfill = smem;
        gA += BK;
        gB += BK;
    }

    // ---- epilogue ----
    const int er = m0 + wm + (lane >> 2);
    const int ec = n0 + wn + ((lane & 3) << 1);
    #pragma unroll
    for (int mi = 0; mi < 4; mi++) {
        #pragma unroll
        for (int nj = 0; nj < 4; nj++) {
            const int row = er + mi * 16;
            const int col = ec + nj * 8;
            float2 bv = *reinterpret_cast<const float2*>(&bias[col]);
            float2 v0 = { acc[mi][nj][0] + bv.x, acc[mi][nj][1] + bv.y };
            float2 v1 = { acc[mi][nj][2] + bv.x, acc[mi][nj][3] + bv.y };
            *reinterpret_cast<float2*>(&out[(size_t)row * OUT_F + col]) = v0;
            *reinterpret_cast<float2*>(&out[(size_t)(row + 8) * OUT_F + col]) = v1;
        }
    }
}

// ---------------------------------------------------------------------------
// Host
// ---------------------------------------------------------------------------
extern "C" void kernel_launch(void* const* d_in, const int* in_sizes, int n_in,
                              void* d_out, int out_size)
{
    const float* x      = (const float*)d_in[0];
    const int*   w_idx  = (const int*)d_in[1];
    const float* absmax = (const float*)d_in[2];
    const float* bias   = (const float*)d_in[3];
    float*       out    = (float*)d_out;

    prep_kernel<<<WB + XB, 256>>>(x, w_idx, absmax);

    cudaFuncSetAttribute(gemm_kernel, cudaFuncAttributeMaxDynamicSharedMemorySize, SMEM_DYN);
    gemm_kernel<<<TILES_M * TILES_N, 256, SMEM_DYN>>>(bias, out);
    (void)in_sizes; (void)n_in; (void)out_size;
}